// round 13
// baseline (speedup 1.0000x reference)
#include <cuda_runtime.h>
#include <math.h>

#define BB 16
#define NN 64
#define TT 50
#define DD 4
#define NEMB 128
#define EPS 1e-20f

#define LOG2E       1.4426950408889634f
#define SELU_SCALE  1.0507009873554805f
#define SELU_SALPHA 1.7580993408473766f           // scale * alpha
#define POS_MUL     (SELU_SCALE / LOG2E)          // a=z*log2e -> scale*z

__device__ __forceinline__ float ex2f(float a) {
    float d; asm("ex2.approx.f32 %0, %1;" : "=f"(d) : "f"(a)); return d;
}
__device__ __forceinline__ float rsqrt_approx(float a) {
    float d; asm("rsqrt.approx.f32 %0, %1;" : "=f"(d) : "f"(a)); return d;
}
// d = (c >= 0) ? a : b
__device__ __forceinline__ float slctf(float a, float b, float c) {
    float d; asm("slct.f32.f32 %0, %1, %2, %3;" : "=f"(d) : "f"(a), "f"(b), "f"(c));
    return d;
}

// a = z * log2e. selu(z) = z>0 ? scale*z : salpha*(e^z - 1)
__device__ __forceinline__ float selu_from_a(float a) {
    const float e   = ex2f(a);
    const float neg = SELU_SALPHA * e - SELU_SALPHA;
    const float pos = a * POS_MUL;
    return slctf(pos, neg, a);
}

__global__ __launch_bounds__(256, 6)
void gcn_split_kernel(const float* __restrict__ x,
                      const float* __restrict__ Wc,
                      const float* __restrict__ bc,
                      const float* __restrict__ Ws,
                      const float* __restrict__ bs,
                      float* __restrict__ out)
{
    const bool is_conv = (blockIdx.x < BB * TT);
    const int bt  = is_conv ? blockIdx.x : (blockIdx.x - BB * TT);
    const int b   = bt / TT;
    const int t   = bt % TT;
    const int tid = threadIdx.x;

    __shared__ float4 sx[NN];            // x[b, :, t, :]
    __shared__ float4 sv[NN];            // epilogue input (conv: sy; skip: = sx)
    __shared__ float  pdeg[4 * NN];
    __shared__ float4 psum[4 * NN];
    __shared__ float  dinv[NN];

    // ---- load x tile (both block types) ----
    if (tid < NN) {
        const float4* p = reinterpret_cast<const float4*>(
            x + ((size_t)(b * NN + tid) * TT + t) * DD);
        sx[tid] = *p;
    }
    __syncthreads();

    if (is_conv) {
        // ---- phase 1: thread (r = tid&63, q = tid>>6) owns m in [16q,16q+16) ----
        const int r = tid & 63;
        const int q = tid >> 6;
        float wv[16];
        {
            const float4 a = sx[r];
            float degp = 0.f;
            #pragma unroll
            for (int k = 0; k < 16; k++) {
                const int m = q * 16 + k;
                const float4 c = sx[m];
                const float d0 = a.x - c.x, d1 = a.y - c.y;
                const float d2 = a.z - c.z, d3 = a.w - c.w;
                float dd = d0 * d0 + d1 * d1 + d2 * d2 + d3 * d3;
                dd = (m == r) ? __int_as_float(0x7f800000) : dd;  // rsqrt(inf)=0
                const float w_ = rsqrt_approx(dd);
                wv[k] = w_;
                degp += w_;
            }
            pdeg[q * NN + r] = degp;
        }
        __syncthreads();

        // ---- dinv + pre-scaled x (reuse psum region for sxd) ----
        float4* sxd = psum + 3 * NN;  // alias: safe, psum written after this read phase? no -> use dedicated trick below
        // NOTE: keep it simple and correct: use pdeg's float4 view is too small;
        // just recompute from dinv in phase 2 (dinv[m] lookup).
        if (tid < NN) {
            const float deg = pdeg[tid] + pdeg[NN + tid] + pdeg[2 * NN + tid] + pdeg[3 * NN + tid];
            const float di  = rsqrt_approx(deg + EPS);
            dinv[tid] = di;
        }
        __syncthreads();

        // ---- phase 2: partial y; scale by dinv[m] inline ----
        {
            float4 acc = make_float4(0.f, 0.f, 0.f, 0.f);
            #pragma unroll
            for (int k = 0; k < 16; k++) {
                const int m = q * 16 + k;
                const float w_ = wv[k] * dinv[m];
                const float4 v = sx[m];
                acc.x += w_ * v.x; acc.y += w_ * v.y;
                acc.z += w_ * v.z; acc.w += w_ * v.w;
            }
            psum[q * NN + r] = acc;
        }
        __syncthreads();

        if (tid < NN) {
            const float4 a0 = psum[tid];
            const float4 a1 = psum[NN + tid];
            const float4 a2 = psum[2 * NN + tid];
            const float4 a3 = psum[3 * NN + tid];
            const float di = dinv[tid];
            sv[tid] = make_float4((a0.x + a1.x + a2.x + a3.x) * di,
                                  (a0.y + a1.y + a2.y + a3.y) * di,
                                  (a0.z + a1.z + a2.z + a3.z) * di,
                                  (a0.w + a1.w + a2.w + a3.w) * di);
        }
        __syncthreads();
    }

    // ---- epilogue: 64 nodes x 128 channels (conv: 128..255, skip: 0..127) ----
    const int cg = tid & 31;             // float4 channel group within the half
    const int ch = cg * 4;               // channel within W (0..124)
    const float* Wp = is_conv ? Wc : Ws;
    const float* bp = is_conv ? bc : bs;

    float4 r0 = *reinterpret_cast<const float4*>(Wp + 0 * NEMB + ch);
    float4 r1 = *reinterpret_cast<const float4*>(Wp + 1 * NEMB + ch);
    float4 r2 = *reinterpret_cast<const float4*>(Wp + 2 * NEMB + ch);
    float4 r3 = *reinterpret_cast<const float4*>(Wp + 3 * NEMB + ch);
    float4 bb = *reinterpret_cast<const float4*>(bp + ch);
    r0.x *= LOG2E; r0.y *= LOG2E; r0.z *= LOG2E; r0.w *= LOG2E;
    r1.x *= LOG2E; r1.y *= LOG2E; r1.z *= LOG2E; r1.w *= LOG2E;
    r2.x *= LOG2E; r2.y *= LOG2E; r2.z *= LOG2E; r2.w *= LOG2E;
    r3.x *= LOG2E; r3.y *= LOG2E; r3.z *= LOG2E; r3.w *= LOG2E;
    bb.x *= LOG2E; bb.y *= LOG2E; bb.z *= LOG2E; bb.w *= LOG2E;

    const int rowq = tid >> 5;           // 0..7 : node row slot
    const float4* vbase = is_conv ? sv : sx;
    const int cbase = is_conv ? (NEMB + ch) : ch;   // output channel offset

    float* obase = out + (((size_t)(b * NN) * TT + t) * 2 * NEMB + cbase);
    const size_t orow = (size_t)TT * 2 * NEMB;

    #pragma unroll
    for (int it = 0; it < 8; it++) {
        const int n = it * 8 + rowq;
        const float4 v = vbase[n];
        float a0 = v.x * r0.x + v.y * r1.x + v.z * r2.x + v.w * r3.x + bb.x;
        float a1 = v.x * r0.y + v.y * r1.y + v.z * r2.y + v.w * r3.y + bb.y;
        float a2 = v.x * r0.z + v.y * r1.z + v.z * r2.z + v.w * r3.z + bb.z;
        float a3 = v.x * r0.w + v.y * r1.w + v.z * r2.w + v.w * r3.w + bb.w;
        float4 o = make_float4(selu_from_a(a0), selu_from_a(a1),
                               selu_from_a(a2), selu_from_a(a3));
        *reinterpret_cast<float4*>(obase + (size_t)n * orow) = o;
    }
}

extern "C" void kernel_launch(void* const* d_in, const int* in_sizes, int n_in,
                              void* d_out, int out_size)
{
    // metadata order: x, rel_rec, rel_send, W_conv, b_conv, W_skip, b_skip
    const float* x  = (const float*)d_in[0];
    const float* Wc = (const float*)d_in[3];
    const float* bc = (const float*)d_in[4];
    const float* Ws = (const float*)d_in[5];
    const float* bs = (const float*)d_in[6];
    float* out = (float*)d_out;

    gcn_split_kernel<<<2 * BB * TT, 256>>>(x, Wc, bc, Ws, bs, out);
}

// round 14
// speedup vs baseline: 1.1026x; 1.1026x over previous
#include <cuda_runtime.h>
#include <math.h>

#define BB 16
#define NN 64
#define TT 50
#define DD 4
#define NEMB 128
#define EPS 1e-20f

#define LOG2E       1.4426950408889634f
#define SELU_SCALE  1.0507009873554805f
#define SELU_SALPHA 1.7580993408473766f           // scale * alpha
#define POS_MUL     (SELU_SCALE / LOG2E)          // a=z*log2e -> scale*z

__device__ __forceinline__ float ex2f(float a) {
    float d; asm("ex2.approx.f32 %0, %1;" : "=f"(d) : "f"(a)); return d;
}
__device__ __forceinline__ float rsqrt_approx(float a) {
    float d; asm("rsqrt.approx.f32 %0, %1;" : "=f"(d) : "f"(a)); return d;
}
// d = (c >= 0) ? a : b
__device__ __forceinline__ float slctf(float a, float b, float c) {
    float d; asm("slct.f32.f32 %0, %1, %2, %3;" : "=f"(d) : "f"(a), "f"(b), "f"(c));
    return d;
}

// a = z * log2e. selu(z) = z>0 ? scale*z : salpha*(e^z - 1)
__device__ __forceinline__ float selu_from_a(float a) {
    const float e   = ex2f(a);
    const float neg = SELU_SALPHA * e - SELU_SALPHA;
    const float pos = a * POS_MUL;
    return slctf(pos, neg, a);
}

__global__ __launch_bounds__(256)
void gcn_fused_kernel(const float* __restrict__ x,
                      const float* __restrict__ Wc,
                      const float* __restrict__ bc,
                      const float* __restrict__ Ws,
                      const float* __restrict__ bs,
                      float* __restrict__ out)
{
    const int bt  = blockIdx.x;          // 0..B*T-1
    const int b   = bt / TT;
    const int t   = bt % TT;
    const int tid = threadIdx.x;

    __shared__ float4 sx[NN];            // x[b, :, t, :]
    __shared__ float4 sxd[NN];           // dinv[m] * x[m]
    __shared__ float4 sy[NN];            // normalized conv input
    __shared__ float  pdeg[4 * NN];      // partial degree sums
    __shared__ float4 psum[4 * NN];      // partial y sums
    __shared__ float  dinv[NN];

    // ---- load x tile ----
    if (tid < NN) {
        const float4* p = reinterpret_cast<const float4*>(
            x + ((size_t)(b * NN + tid) * TT + t) * DD);
        sx[tid] = *p;
    }
    __syncthreads();

    // epilogue thread mapping (shared by both halves):
    // cg = channel float4 group within the 128-channel half (0..31)
    // rowq = node-row slot (0..7), 8 iterations cover 64 nodes
    const int cg   = tid & 31;
    const int ch   = cg * 4;
    const int rowq = tid >> 5;
    float* orow0 = out + (((size_t)(b * NN) * TT + t) * 2 * NEMB);
    const size_t orow = (size_t)TT * 2 * NEMB;

    // ================= SKIP epilogue first: depends only on sx ==============
    {
        float4 r0 = *reinterpret_cast<const float4*>(Ws + 0 * NEMB + ch);
        float4 r1 = *reinterpret_cast<const float4*>(Ws + 1 * NEMB + ch);
        float4 r2 = *reinterpret_cast<const float4*>(Ws + 2 * NEMB + ch);
        float4 r3 = *reinterpret_cast<const float4*>(Ws + 3 * NEMB + ch);
        float4 bb = *reinterpret_cast<const float4*>(bs + ch);
        r0.x *= LOG2E; r0.y *= LOG2E; r0.z *= LOG2E; r0.w *= LOG2E;
        r1.x *= LOG2E; r1.y *= LOG2E; r1.z *= LOG2E; r1.w *= LOG2E;
        r2.x *= LOG2E; r2.y *= LOG2E; r2.z *= LOG2E; r2.w *= LOG2E;
        r3.x *= LOG2E; r3.y *= LOG2E; r3.z *= LOG2E; r3.w *= LOG2E;
        bb.x *= LOG2E; bb.y *= LOG2E; bb.z *= LOG2E; bb.w *= LOG2E;

        float* ob = orow0 + ch;          // skip channels 0..127
        #pragma unroll
        for (int it = 0; it < 8; it++) {
            const int n = it * 8 + rowq;
            const float4 v = sx[n];
            float a0 = v.x * r0.x + v.y * r1.x + v.z * r2.x + v.w * r3.x + bb.x;
            float a1 = v.x * r0.y + v.y * r1.y + v.z * r2.y + v.w * r3.y + bb.y;
            float a2 = v.x * r0.z + v.y * r1.z + v.z * r2.z + v.w * r3.z + bb.z;
            float a3 = v.x * r0.w + v.y * r1.w + v.z * r2.w + v.w * r3.w + bb.w;
            float4 o = make_float4(selu_from_a(a0), selu_from_a(a1),
                                   selu_from_a(a2), selu_from_a(a3));
            *reinterpret_cast<float4*>(ob + (size_t)n * orow) = o;
        }
    }

    // ================= phases 1-3 (unchanged from R7) ========================
    const int r = tid & 63;
    const int q = tid >> 6;
    float wv[16];
    {
        const float4 a = sx[r];
        float degp = 0.f;
        #pragma unroll
        for (int k = 0; k < 16; k++) {
            const int m = q * 16 + k;
            const float4 c = sx[m];
            const float d0 = a.x - c.x, d1 = a.y - c.y;
            const float d2 = a.z - c.z, d3 = a.w - c.w;
            float dd = d0 * d0 + d1 * d1 + d2 * d2 + d3 * d3;
            dd = (m == r) ? __int_as_float(0x7f800000) : dd;   // rsqrt(inf)=0
            const float w_ = rsqrt_approx(dd);
            wv[k] = w_;
            degp += w_;
        }
        pdeg[q * NN + r] = degp;
    }
    __syncthreads();

    if (tid < NN) {
        const float deg = pdeg[tid] + pdeg[NN + tid] + pdeg[2 * NN + tid] + pdeg[3 * NN + tid];
        const float di  = rsqrt_approx(deg + EPS);
        dinv[tid] = di;
        const float4 v = sx[tid];
        sxd[tid] = make_float4(v.x * di, v.y * di, v.z * di, v.w * di);
    }
    __syncthreads();

    {
        float4 acc = make_float4(0.f, 0.f, 0.f, 0.f);
        #pragma unroll
        for (int k = 0; k < 16; k++) {
            const int m = q * 16 + k;
            const float w_ = wv[k];
            const float4 v = sxd[m];
            acc.x += w_ * v.x; acc.y += w_ * v.y;
            acc.z += w_ * v.z; acc.w += w_ * v.w;
        }
        psum[q * NN + r] = acc;
    }
    // wv[] dead -> load conv weights here, reusing those registers (R9 trick)
    float4 r0 = *reinterpret_cast<const float4*>(Wc + 0 * NEMB + ch);
    float4 r1 = *reinterpret_cast<const float4*>(Wc + 1 * NEMB + ch);
    float4 r2 = *reinterpret_cast<const float4*>(Wc + 2 * NEMB + ch);
    float4 r3 = *reinterpret_cast<const float4*>(Wc + 3 * NEMB + ch);
    float4 bb = *reinterpret_cast<const float4*>(bc + ch);
    __syncthreads();

    if (tid < NN) {
        const float4 a0 = psum[tid];
        const float4 a1 = psum[NN + tid];
        const float4 a2 = psum[2 * NN + tid];
        const float4 a3 = psum[3 * NN + tid];
        const float di = dinv[tid];
        sy[tid] = make_float4((a0.x + a1.x + a2.x + a3.x) * di,
                              (a0.y + a1.y + a2.y + a3.y) * di,
                              (a0.z + a1.z + a2.z + a3.z) * di,
                              (a0.w + a1.w + a2.w + a3.w) * di);
    }
    r0.x *= LOG2E; r0.y *= LOG2E; r0.z *= LOG2E; r0.w *= LOG2E;
    r1.x *= LOG2E; r1.y *= LOG2E; r1.z *= LOG2E; r1.w *= LOG2E;
    r2.x *= LOG2E; r2.y *= LOG2E; r2.z *= LOG2E; r2.w *= LOG2E;
    r3.x *= LOG2E; r3.y *= LOG2E; r3.z *= LOG2E; r3.w *= LOG2E;
    bb.x *= LOG2E; bb.y *= LOG2E; bb.z *= LOG2E; bb.w *= LOG2E;
    __syncthreads();

    // ================= CONV epilogue: channels 128..255 ======================
    {
        float* ob = orow0 + NEMB + ch;
        #pragma unroll
        for (int it = 0; it < 8; it++) {
            const int n = it * 8 + rowq;
            const float4 v = sy[n];
            float a0 = v.x * r0.x + v.y * r1.x + v.z * r2.x + v.w * r3.x + bb.x;
            float a1 = v.x * r0.y + v.y * r1.y + v.z * r2.y + v.w * r3.y + bb.y;
            float a2 = v.x * r0.z + v.y * r1.z + v.z * r2.z + v.w * r3.z + bb.z;
            float a3 = v.x * r0.w + v.y * r1.w + v.z * r2.w + v.w * r3.w + bb.w;
            float4 o = make_float4(selu_from_a(a0), selu_from_a(a1),
                                   selu_from_a(a2), selu_from_a(a3));
            *reinterpret_cast<float4*>(ob + (size_t)n * orow) = o;
        }
    }
}

extern "C" void kernel_launch(void* const* d_in, const int* in_sizes, int n_in,
                              void* d_out, int out_size)
{
    // metadata order: x, rel_rec, rel_send, W_conv, b_conv, W_skip, b_skip
    const float* x  = (const float*)d_in[0];
    const float* Wc = (const float*)d_in[3];
    const float* bc = (const float*)d_in[4];
    const float* Ws = (const float*)d_in[5];
    const float* bs = (const float*)d_in[6];
    float* out = (float*)d_out;

    gcn_fused_kernel<<<BB * TT, 256>>>(x, Wc, bc, Ws, bs, out);
}

// round 15
// speedup vs baseline: 1.2037x; 1.0916x over previous
#include <cuda_runtime.h>
#include <math.h>

#define BB 16
#define NN 64
#define TT 50
#define DD 4
#define NEMB 128
#define EPS 1e-20f

#define LOG2E       1.4426950408889634f
#define SELU_SCALE  1.0507009873554805f
#define SELU_SALPHA 1.7580993408473766f           // scale * alpha
#define POS_MUL     (SELU_SCALE / LOG2E)          // a=z*log2e -> scale*z

__device__ __forceinline__ float ex2f(float a) {
    float d; asm("ex2.approx.f32 %0, %1;" : "=f"(d) : "f"(a)); return d;
}
// d = (c >= 0) ? a : b
__device__ __forceinline__ float slctf(float a, float b, float c) {
    float d; asm("slct.f32.f32 %0, %1, %2, %3;" : "=f"(d) : "f"(a), "f"(b), "f"(c));
    return d;
}

// a = z * log2e. selu(z) = z>0 ? scale*z : salpha*(e^z - 1)
__device__ __forceinline__ float selu_from_a(float a) {
    const float e   = ex2f(a);
    const float neg = SELU_SALPHA * e - SELU_SALPHA;
    const float pos = a * POS_MUL;
    return slctf(pos, neg, a);
}

__global__ __launch_bounds__(256)
void gcn_fused_kernel(const float* __restrict__ x,
                      const float* __restrict__ Wc,
                      const float* __restrict__ bc,
                      const float* __restrict__ Ws,
                      const float* __restrict__ bs,
                      float* __restrict__ out)
{
    const int bt  = blockIdx.x;          // 0..B*T-1
    const int b   = bt / TT;
    const int t   = bt % TT;
    const int tid = threadIdx.x;

    __shared__ float4 sx[NN];            // x[b, :, t, :]
    __shared__ float4 sxd[NN];           // dinv[m] * x[m]
    __shared__ float4 sy[NN];            // normalized conv input
    __shared__ float  pdeg[4 * NN];      // partial degree sums
    __shared__ float4 psum[4 * NN];      // partial y sums
    __shared__ float  dinv[NN];

    // ---- load x tile ----
    if (tid < NN) {
        const float4* p = reinterpret_cast<const float4*>(
            x + ((size_t)(b * NN + tid) * TT + t) * DD);
        sx[tid] = *p;
    }
    __syncthreads();

    // ---- phase 1: thread (r = tid&63, q = tid>>6) owns m in [16q, 16q+16) ----
    const int r = tid & 63;
    const int q = tid >> 6;
    float wv[16];
    {
        const float4 a = sx[r];
        float degp = 0.f;
        #pragma unroll
        for (int k = 0; k < 16; k++) {
            const int m = q * 16 + k;
            const float4 c = sx[m];
            const float d0 = a.x - c.x, d1 = a.y - c.y;
            const float d2 = a.z - c.z, d3 = a.w - c.w;
            const float dd = d0 * d0 + d1 * d1 + d2 * d2 + d3 * d3;
            const float w_ = (m == r) ? 0.f : rsqrtf(dd);  // 1/(||.||+1e-20) ~ rsqrt
            wv[k] = w_;
            degp += w_;
        }
        pdeg[q * NN + r] = degp;
    }
    __syncthreads();

    // ---- dinv + pre-scaled x ----
    if (tid < NN) {
        const float deg = pdeg[tid] + pdeg[NN + tid] + pdeg[2 * NN + tid] + pdeg[3 * NN + tid];
        const float di  = rsqrtf(deg + EPS);
        dinv[tid] = di;
        const float4 v = sx[tid];
        sxd[tid] = make_float4(v.x * di, v.y * di, v.z * di, v.w * di);
    }
    __syncthreads();

    // ---- phase 2: partial y from register-held weights ----
    {
        float4 acc = make_float4(0.f, 0.f, 0.f, 0.f);
        #pragma unroll
        for (int k = 0; k < 16; k++) {
            const int m = q * 16 + k;
            const float w_ = wv[k];
            const float4 v = sxd[m];
            acc.x += w_ * v.x; acc.y += w_ * v.y;
            acc.z += w_ * v.z; acc.w += w_ * v.w;
        }
        psum[q * NN + r] = acc;
    }
    __syncthreads();

    if (tid < NN) {
        const float4 a0 = psum[tid];
        const float4 a1 = psum[NN + tid];
        const float4 a2 = psum[2 * NN + tid];
        const float4 a3 = psum[3 * NN + tid];
        const float di = dinv[tid];
        sy[tid] = make_float4((a0.x + a1.x + a2.x + a3.x) * di,
                              (a0.y + a1.y + a2.y + a3.y) * di,
                              (a0.z + a1.z + a2.z + a3.z) * di,
                              (a0.w + a1.w + a2.w + a3.w) * di);
    }
    __syncthreads();

    // ---- epilogue: 64 nodes x 256 channels, weights pre-scaled by log2e ----
    const int rowq = tid >> 6;           // which of 4 node rows per iter
    const int cg   = tid & 63;           // float4 channel group
    const int cc   = cg * 4;
    const bool is_skip = (cc < NEMB);
    const int  ch      = is_skip ? cc : (cc - NEMB);
    const float* Wp = is_skip ? Ws : Wc;
    const float* bp = is_skip ? bs : bc;
    const float4* vbase = is_skip ? sx : sy;

    float4 r0 = *reinterpret_cast<const float4*>(Wp + 0 * NEMB + ch);
    float4 r1 = *reinterpret_cast<const float4*>(Wp + 1 * NEMB + ch);
    float4 r2 = *reinterpret_cast<const float4*>(Wp + 2 * NEMB + ch);
    float4 r3 = *reinterpret_cast<const float4*>(Wp + 3 * NEMB + ch);
    float4 bb = *reinterpret_cast<const float4*>(bp + ch);
    r0.x *= LOG2E; r0.y *= LOG2E; r0.z *= LOG2E; r0.w *= LOG2E;
    r1.x *= LOG2E; r1.y *= LOG2E; r1.z *= LOG2E; r1.w *= LOG2E;
    r2.x *= LOG2E; r2.y *= LOG2E; r2.z *= LOG2E; r2.w *= LOG2E;
    r3.x *= LOG2E; r3.y *= LOG2E; r3.z *= LOG2E; r3.w *= LOG2E;
    bb.x *= LOG2E; bb.y *= LOG2E; bb.z *= LOG2E; bb.w *= LOG2E;

    float* obase = out + (((size_t)(b * NN) * TT + t) * 2 * NEMB + cc);
    const size_t orow = (size_t)TT * 2 * NEMB;

    #pragma unroll
    for (int it = 0; it < 16; it++) {
        const int n = it * 4 + rowq;
        const float4 v = vbase[n];
        // a = (v . W + b) * log2e
        float a0 = v.x * r0.x + v.y * r1.x + v.z * r2.x + v.w * r3.x + bb.x;
        float a1 = v.x * r0.y + v.y * r1.y + v.z * r2.y + v.w * r3.y + bb.y;
        float a2 = v.x * r0.z + v.y * r1.z + v.z * r2.z + v.w * r3.z + bb.z;
        float a3 = v.x * r0.w + v.y * r1.w + v.z * r2.w + v.w * r3.w + bb.w;
        float4 o = make_float4(selu_from_a(a0), selu_from_a(a1),
                               selu_from_a(a2), selu_from_a(a3));
        *reinterpret_cast<float4*>(obase + (size_t)n * orow) = o;
    }
}

extern "C" void kernel_launch(void* const* d_in, const int* in_sizes, int n_in,
                              void* d_out, int out_size)
{
    // metadata order: x, rel_rec, rel_send, W_conv, b_conv, W_skip, b_skip
    const float* x  = (const float*)d_in[0];
    const float* Wc = (const float*)d_in[3];
    const float* bc = (const float*)d_in[4];
    const float* Ws = (const float*)d_in[5];
    const float* bs = (const float*)d_in[6];
    float* out = (float*)d_out;

    gcn_fused_kernel<<<BB * TT, 256>>>(x, Wc, bc, Ws, bs, out);
}

// round 16
// speedup vs baseline: 1.2765x; 1.0605x over previous
#include <cuda_runtime.h>
#include <math.h>

#define BB 16
#define NN 64
#define TT 50
#define DD 4
#define NEMB 128
#define EPS 1e-20f

#define LOG2E       1.4426950408889634f
#define SELU_SCALE  1.0507009873554805f
#define SELU_SALPHA 1.7580993408473766f           // scale * alpha
#define POS_MUL     (SELU_SCALE / LOG2E)          // a=z*log2e -> scale*z

__device__ __forceinline__ float ex2f(float a) {
    float d; asm("ex2.approx.f32 %0, %1;" : "=f"(d) : "f"(a)); return d;
}
// d = (c >= 0) ? a : b
__device__ __forceinline__ float slctf(float a, float b, float c) {
    float d; asm("slct.f32.f32 %0, %1, %2, %3;" : "=f"(d) : "f"(a), "f"(b), "f"(c));
    return d;
}

// a = z * log2e. selu(z) = z>0 ? scale*z : salpha*(e^z - 1)
__device__ __forceinline__ float selu_from_a(float a) {
    const float e   = ex2f(a);
    const float neg = SELU_SALPHA * e - SELU_SALPHA;
    const float pos = a * POS_MUL;
    return slctf(pos, neg, a);
}

__global__ __launch_bounds__(256)
void gcn_fused_kernel(const float* __restrict__ x,
                      const float* __restrict__ Wc,
                      const float* __restrict__ bc,
                      const float* __restrict__ Ws,
                      const float* __restrict__ bs,
                      float* __restrict__ out)
{
    const int bt  = blockIdx.x;          // 0..B*T-1
    const int b   = bt / TT;
    const int t   = bt % TT;
    const int tid = threadIdx.x;

    __shared__ float4 sx[NN];            // x[b, :, t, :]
    __shared__ float4 sxd[NN];           // dinv[m] * x[m]
    __shared__ float4 sy[NN];            // normalized conv input
    __shared__ float  pdeg[4 * NN];      // partial degree sums
    __shared__ float4 psum[4 * NN];      // partial y sums
    __shared__ float  dinv[NN];

    // ---- load x tile: 128 threads x float2 (halves fill latency) ----
    if (tid < 2 * NN) {
        const int n    = tid >> 1;
        const int half = tid & 1;
        const float2* p = reinterpret_cast<const float2*>(
            x + ((size_t)(b * NN + n) * TT + t) * DD) + half;
        reinterpret_cast<float2*>(&sx[n])[half] = *p;
    }
    __syncthreads();

    // ---- phase 1: thread (r = tid&63, q = tid>>6) owns m in [16q, 16q+16) ----
    const int r = tid & 63;
    const int q = tid >> 6;
    float wv[16];
    {
        const float4 a = sx[r];
        float degp = 0.f;
        #pragma unroll
        for (int k = 0; k < 16; k++) {
            const int m = q * 16 + k;
            const float4 c = sx[m];
            const float d0 = a.x - c.x, d1 = a.y - c.y;
            const float d2 = a.z - c.z, d3 = a.w - c.w;
            const float dd = d0 * d0 + d1 * d1 + d2 * d2 + d3 * d3;
            const float w_ = (m == r) ? 0.f : rsqrtf(dd);  // 1/(||.||+1e-20) ~ rsqrt
            wv[k] = w_;
            degp += w_;
        }
        pdeg[q * NN + r] = degp;
    }
    __syncthreads();

    // ---- dinv + pre-scaled x ----
    if (tid < NN) {
        const float deg = pdeg[tid] + pdeg[NN + tid] + pdeg[2 * NN + tid] + pdeg[3 * NN + tid];
        const float di  = rsqrtf(deg + EPS);
        dinv[tid] = di;
        const float4 v = sx[tid];
        sxd[tid] = make_float4(v.x * di, v.y * di, v.z * di, v.w * di);
    }
    __syncthreads();

    // ---- phase 2: partial y from register-held weights ----
    {
        float4 acc = make_float4(0.f, 0.f, 0.f, 0.f);
        #pragma unroll
        for (int k = 0; k < 16; k++) {
            const int m = q * 16 + k;
            const float w_ = wv[k];
            const float4 v = sxd[m];
            acc.x += w_ * v.x; acc.y += w_ * v.y;
            acc.z += w_ * v.z; acc.w += w_ * v.w;
        }
        psum[q * NN + r] = acc;
    }
    __syncthreads();

    if (tid < NN) {
        const float4 a0 = psum[tid];
        const float4 a1 = psum[NN + tid];
        const float4 a2 = psum[2 * NN + tid];
        const float4 a3 = psum[3 * NN + tid];
        const float di = dinv[tid];
        sy[tid] = make_float4((a0.x + a1.x + a2.x + a3.x) * di,
                              (a0.y + a1.y + a2.y + a3.y) * di,
                              (a0.z + a1.z + a2.z + a3.z) * di,
                              (a0.w + a1.w + a2.w + a3.w) * di);
    }
    __syncthreads();

    // ---- epilogue: 64 nodes x 256 channels, weights pre-scaled by log2e ----
    const int rowq = tid >> 6;           // which of 4 node rows per iter
    const int cg   = tid & 63;           // float4 channel group
    const int cc   = cg * 4;
    const bool is_skip = (cc < NEMB);
    const int  ch      = is_skip ? cc : (cc - NEMB);
    const float* Wp = is_skip ? Ws : Wc;
    const float* bp = is_skip ? bs : bc;
    const float4* vbase = is_skip ? sx : sy;

    float4 r0 = *reinterpret_cast<const float4*>(Wp + 0 * NEMB + ch);
    float4 r1 = *reinterpret_cast<const float4*>(Wp + 1 * NEMB + ch);
    float4 r2 = *reinterpret_cast<const float4*>(Wp + 2 * NEMB + ch);
    float4 r3 = *reinterpret_cast<const float4*>(Wp + 3 * NEMB + ch);
    float4 bb = *reinterpret_cast<const float4*>(bp + ch);
    r0.x *= LOG2E; r0.y *= LOG2E; r0.z *= LOG2E; r0.w *= LOG2E;
    r1.x *= LOG2E; r1.y *= LOG2E; r1.z *= LOG2E; r1.w *= LOG2E;
    r2.x *= LOG2E; r2.y *= LOG2E; r2.z *= LOG2E; r2.w *= LOG2E;
    r3.x *= LOG2E; r3.y *= LOG2E; r3.z *= LOG2E; r3.w *= LOG2E;
    bb.x *= LOG2E; bb.y *= LOG2E; bb.z *= LOG2E; bb.w *= LOG2E;

    // 32-bit store offsets: per-block slice is < 2^31 bytes, so n*orow fits int
    float4* obase = reinterpret_cast<float4*>(
        out + (((size_t)(b * NN) * TT + t) * 2 * NEMB + cc));
    const int orow4 = TT * 2 * NEMB / 4;     // float4 units between node rows

    #pragma unroll
    for (int it = 0; it < 16; it++) {
        const int n = it * 4 + rowq;
        const float4 v = vbase[n];
        // a = (v . W + b) * log2e
        float a0 = v.x * r0.x + v.y * r1.x + v.z * r2.x + v.w * r3.x + bb.x;
        float a1 = v.x * r0.y + v.y * r1.y + v.z * r2.y + v.w * r3.y + bb.y;
        float a2 = v.x * r0.z + v.y * r1.z + v.z * r2.z + v.w * r3.z + bb.z;
        float a3 = v.x * r0.w + v.y * r1.w + v.z * r2.w + v.w * r3.w + bb.w;
        float4 o = make_float4(selu_from_a(a0), selu_from_a(a1),
                               selu_from_a(a2), selu_from_a(a3));
        obase[n * orow4] = o;
    }
}

extern "C" void kernel_launch(void* const* d_in, const int* in_sizes, int n_in,
                              void* d_out, int out_size)
{
    // metadata order: x, rel_rec, rel_send, W_conv, b_conv, W_skip, b_skip
    const float* x  = (const float*)d_in[0];
    const float* Wc = (const float*)d_in[3];
    const float* bc = (const float*)d_in[4];
    const float* Ws = (const float*)d_in[5];
    const float* bs = (const float*)d_in[6];
    float* out = (float*)d_out;

    gcn_fused_kernel<<<BB * TT, 256>>>(x, Wc, bc, Ws, bs, out);
}